// round 1
// baseline (speedup 1.0000x reference)
#include <cuda_runtime.h>
#include <math.h>

// Problem constants
#define BB 2
#define SS 8192
#define CC 64
#define MMG 32
#define GG (SS / MMG)          // 256 groups per batch
#define BCS (BB * CC * SS)

// Scratch (device globals — allocation-free)
__device__ float g_Pf[BCS];    // b1_0 + W1_0[:,0:3]@xyz1 + W1_0[:,10:74]@feat1
__device__ float g_Qf[BCS];    // W1_0[:,3:6]@xyz2 + W1_0[:,74:138]@feat2
__device__ float g_Pe[BCS];    // bxyz1 + Wxyz1[:,0:3]@xyz1
__device__ float g_Qe[BCS];    // Wxyz1[:,3:6]@xyz2
__device__ float g_Ef[BCS];    // bxyz2 + Wxyz2[:,0:3]@xyz1
__device__ float g_Eg[BCS];    // Wxyz2[:,3:6]@xyz1   (stage-2 gathers xyz1!)
__device__ float g_F1[BCS];    // b3_0 + W3_0[:,64:128]@feat1
__device__ float g_agg[BCS];   // pi_agg

// ---------------------------------------------------------------------------
// helpers
// ---------------------------------------------------------------------------
__device__ __forceinline__ float warp_rmax(float v) {
#pragma unroll
    for (int o = 16; o > 0; o >>= 1) v = fmaxf(v, __shfl_xor_sync(0xffffffffu, v, o));
    return v;
}
__device__ __forceinline__ float warp_rsum(float v) {
#pragma unroll
    for (int o = 16; o > 0; o >>= 1) v += __shfl_xor_sync(0xffffffffu, v, o);
    return v;
}

// acc[i] += W[cbase+i, :64] . A[:, lane]   (A stored [cin][32], W row stride = wstride)
__device__ __forceinline__ void mm64_acc(float acc[8], const float* __restrict__ sW,
                                         int wstride, int cbase,
                                         const float* __restrict__ sA, int lane) {
#pragma unroll 4
    for (int q = 0; q < 16; q++) {
        float a0 = sA[(4 * q + 0) * 32 + lane];
        float a1 = sA[(4 * q + 1) * 32 + lane];
        float a2 = sA[(4 * q + 2) * 32 + lane];
        float a3 = sA[(4 * q + 3) * 32 + lane];
#pragma unroll
        for (int i = 0; i < 8; i++) {
            float4 w = *reinterpret_cast<const float4*>(&sW[(cbase + i) * wstride + 4 * q]);
            acc[i] = fmaf(w.x, a0, acc[i]);
            acc[i] = fmaf(w.y, a1, acc[i]);
            acc[i] = fmaf(w.z, a2, acc[i]);
            acc[i] = fmaf(w.w, a3, acc[i]);
        }
    }
}

// ---------------------------------------------------------------------------
// Kernel A: per-point linear projections (decomposed layer-0 parts)
// grid = (BB*SS)/32 blocks, 256 threads; block handles 32 consecutive points
// ---------------------------------------------------------------------------
struct SmemA {
    float Wpf[64 * 64];    // W1_0[:,10:74]
    float Wqf[64 * 64];    // W1_0[:,74:138]
    float Wf1[64 * 64];    // W3_0[:,64:128]
    float W1x[64 * 8];     // W1_0[:,0:6]   ([c*8+j], j<6)
    float Wex[64 * 8];     // Wxyz1[:,0:6]
    float W2x[64 * 8];     // Wxyz2[:,0:6]
    float F1t[64 * 32];
    float F2t[64 * 32];
    float X1[3 * 32];
    float X2[3 * 32];
};

__global__ void kernelA(const float* __restrict__ xyz1, const float* __restrict__ feat1,
                        const float* __restrict__ xyz2, const float* __restrict__ feat2,
                        const float* __restrict__ w10, const float* __restrict__ b10,
                        const float* __restrict__ wx1, const float* __restrict__ bx1,
                        const float* __restrict__ wx2, const float* __restrict__ bx2,
                        const float* __restrict__ w30, const float* __restrict__ b30) {
    extern __shared__ float smem_raw[];
    SmemA& s = *reinterpret_cast<SmemA*>(smem_raw);
    int tid = threadIdx.x;
    int t = blockIdx.x;
    int b = t >> 8;                 // (SS/32)=256 tiles per batch
    int s0 = (t & 255) * 32;

    for (int idx = tid; idx < 4096; idx += 256) {
        int c = idx >> 6, j = idx & 63;
        s.Wpf[idx] = w10[c * 138 + 10 + j];
        s.Wqf[idx] = w10[c * 138 + 74 + j];
        s.Wf1[idx] = w30[c * 192 + 64 + j];
    }
    for (int idx = tid; idx < 384; idx += 256) {
        int c = idx / 6, j = idx % 6;
        s.W1x[c * 8 + j] = w10[c * 138 + j];
        s.Wex[c * 8 + j] = wx1[c * 10 + j];
        s.W2x[c * 8 + j] = wx2[c * 10 + j];
    }
    for (int idx = tid; idx < 2048; idx += 256) {
        int c = idx >> 5, k = idx & 31;
        s.F1t[idx] = feat1[b * CC * SS + c * SS + s0 + k];
        s.F2t[idx] = feat2[b * CC * SS + c * SS + s0 + k];
    }
    for (int idx = tid; idx < 96; idx += 256) {
        int i = idx >> 5, k = idx & 31;
        s.X1[idx] = xyz1[b * 3 * SS + i * SS + s0 + k];
        s.X2[idx] = xyz2[b * 3 * SS + i * SS + s0 + k];
    }
    __syncthreads();

    int lane = tid & 31;
    int cb = (tid >> 5) * 8;
    float x10 = s.X1[lane], x11 = s.X1[32 + lane], x12 = s.X1[64 + lane];
    float x20 = s.X2[lane], x21 = s.X2[32 + lane], x22 = s.X2[64 + lane];

    float accPf[8], accQf[8], accF1[8];
#pragma unroll
    for (int i = 0; i < 8; i++) {
        accPf[i] = __ldg(&b10[cb + i]);
        accQf[i] = 0.f;
        accF1[i] = __ldg(&b30[cb + i]);
    }
    mm64_acc(accPf, s.Wpf, 64, cb, s.F1t, lane);
    mm64_acc(accF1, s.Wf1, 64, cb, s.F1t, lane);
    mm64_acc(accQf, s.Wqf, 64, cb, s.F2t, lane);

#pragma unroll
    for (int i = 0; i < 8; i++) {
        int c = cb + i;
        long base = (long)b * CC * SS + (long)c * SS + s0 + lane;
        float pf = accPf[i] + s.W1x[c * 8 + 0] * x10 + s.W1x[c * 8 + 1] * x11 + s.W1x[c * 8 + 2] * x12;
        float qf = accQf[i] + s.W1x[c * 8 + 3] * x20 + s.W1x[c * 8 + 4] * x21 + s.W1x[c * 8 + 5] * x22;
        g_Pf[base] = pf;
        g_Qf[base] = qf;
        g_F1[base] = accF1[i];
        g_Pe[base] = __ldg(&bx1[c]) + s.Wex[c * 8 + 0] * x10 + s.Wex[c * 8 + 1] * x11 + s.Wex[c * 8 + 2] * x12;
        g_Qe[base] = s.Wex[c * 8 + 3] * x20 + s.Wex[c * 8 + 4] * x21 + s.Wex[c * 8 + 5] * x22;
        g_Ef[base] = __ldg(&bx2[c]) + s.W2x[c * 8 + 0] * x10 + s.W2x[c * 8 + 1] * x11 + s.W2x[c * 8 + 2] * x12;
        g_Eg[base] = s.W2x[c * 8 + 3] * x10 + s.W2x[c * 8 + 4] * x11 + s.W2x[c * 8 + 5] * x12;
    }
}

// ---------------------------------------------------------------------------
// Kernel B: stage 1 — per group, softmax attention over the 32 group members
// grid = BB*GG blocks, 256 threads
// ---------------------------------------------------------------------------
struct SmemB {
    float W11[64 * 64];
    float W20[64 * 128];
    float W21[64 * 64];
    float W1d[64 * 4];     // W1_0[:,6:10]
    float Wed[64 * 4];     // Wxyz1[:,6:10]
    float B11[64], B20[64], B21[64];
    float Pf[64 * 32], Pe[64 * 32];
    float X1[3 * 32], X2[3 * 32];
    float H[64 * 32], PN[64 * 32], PE[64 * 32];
};

__global__ void kernelB(const float* __restrict__ xyz1, const float* __restrict__ xyz2,
                        const float* __restrict__ w10, const float* __restrict__ wx1,
                        const float* __restrict__ w11, const float* __restrict__ b11,
                        const float* __restrict__ w20, const float* __restrict__ b20,
                        const float* __restrict__ w21, const float* __restrict__ b21) {
    extern __shared__ float smem_raw[];
    SmemB& s = *reinterpret_cast<SmemB*>(smem_raw);
    int tid = threadIdx.x;
    int b = blockIdx.x / GG;
    int g = blockIdx.x % GG;
    int sb = g * MMG;

    for (int idx = tid; idx < 4096; idx += 256) {
        s.W11[idx] = w11[idx];
        s.W21[idx] = w21[idx];
    }
    for (int idx = tid; idx < 8192; idx += 256) s.W20[idx] = w20[idx];
    for (int idx = tid; idx < 256; idx += 256) { /* nothing */ }
    for (int idx = tid; idx < 256; idx += 256) ;
    for (int idx = tid; idx < 256; idx += 256) ;
    if (tid < 256) {
        int c = tid >> 2, j = tid & 3;
        s.W1d[tid] = w10[c * 138 + 6 + j];
        s.Wed[tid] = wx1[c * 10 + 6 + j];
    }
    if (tid < 64) {
        s.B11[tid] = b11[tid];
        s.B20[tid] = b20[tid];
        s.B21[tid] = b21[tid];
    }
    for (int idx = tid; idx < 2048; idx += 256) {
        int c = idx >> 5, k = idx & 31;
        long base = (long)b * CC * SS + (long)c * SS + sb + k;
        s.Pf[idx] = g_Pf[base];
        s.Pe[idx] = g_Pe[base];
    }
    for (int idx = tid; idx < 96; idx += 256) {
        int i = idx >> 5, k = idx & 31;
        s.X1[idx] = xyz1[b * 3 * SS + i * SS + sb + k];
        s.X2[idx] = xyz2[b * 3 * SS + i * SS + sb + k];
    }
    __syncthreads();

    int lane = tid & 31;
    int cb = (tid >> 5) * 8;

    // Qf/Qe for this block's columns (independent of s-loop) — hoist into regs
    float qf[8], qe[8];
#pragma unroll
    for (int i = 0; i < 8; i++) {
        long base = (long)b * CC * SS + (long)(cb + i) * SS + sb + lane;
        qf[i] = __ldg(&g_Qf[base]);
        qe[i] = __ldg(&g_Qe[base]);
    }

    for (int sl = 0; sl < MMG; sl++) {
        float px0 = s.X1[sl], px1 = s.X1[32 + sl], px2 = s.X1[64 + sl];
        float d0 = s.X2[lane] - px0;
        float d1 = s.X2[32 + lane] - px1;
        float d2 = s.X2[64 + lane] - px2;
        float euc = sqrtf(d0 * d0 + d1 * d1 + d2 * d2 + 1e-20f);

        // h1 & pi_enc (dynamic 4-channel part + precomputed projections)
#pragma unroll
        for (int i = 0; i < 8; i++) {
            int c = cb + i;
            float h = s.Pf[c * 32 + sl] + qf[i]
                    + s.W1d[c * 4 + 0] * d0 + s.W1d[c * 4 + 1] * d1
                    + s.W1d[c * 4 + 2] * d2 + s.W1d[c * 4 + 3] * euc;
            s.H[c * 32 + lane] = fmaxf(h, 0.f);
            float pe = s.Pe[c * 32 + sl] + qe[i]
                     + s.Wed[c * 4 + 0] * d0 + s.Wed[c * 4 + 1] * d1
                     + s.Wed[c * 4 + 2] * d2 + s.Wed[c * 4 + 3] * euc;
            s.PE[c * 32 + lane] = fmaxf(pe, 0.f);
        }
        __syncthreads();

        // pi_new = relu(W1_1 @ h1 + b1_1)
        float acc[8];
#pragma unroll
        for (int i = 0; i < 8; i++) acc[i] = s.B11[cb + i];
        mm64_acc(acc, s.W11, 64, cb, s.H, lane);
#pragma unroll
        for (int i = 0; i < 8; i++) s.PN[(cb + i) * 32 + lane] = fmaxf(acc[i], 0.f);
        __syncthreads();

        // u = relu(W2_0 @ [pi_enc; pi_new] + b2_0)  -> reuse H
#pragma unroll
        for (int i = 0; i < 8; i++) acc[i] = s.B20[cb + i];
        mm64_acc(acc, s.W20, 128, cb, s.PE, lane);
        mm64_acc(acc, s.W20 + 64, 128, cb, s.PN, lane);
#pragma unroll
        for (int i = 0; i < 8; i++) s.H[(cb + i) * 32 + lane] = fmaxf(acc[i], 0.f);
        __syncthreads();

        // logits = relu(W2_1 @ u + b2_1); softmax over 32 cols; aggregate pi_new
#pragma unroll
        for (int i = 0; i < 8; i++) acc[i] = s.B21[cb + i];
        mm64_acc(acc, s.W21, 64, cb, s.H, lane);
#pragma unroll
        for (int i = 0; i < 8; i++) {
            float l = fmaxf(acc[i], 0.f);
            float m = warp_rmax(l);
            float e = expf(l - m);
            float ssum = warp_rsum(e);
            float wgt = e / ssum;
            float v = warp_rsum(wgt * s.PN[(cb + i) * 32 + lane]);
            if (lane == 0)
                g_agg[(long)b * CC * SS + (long)(cb + i) * SS + sb + sl] = v;
        }
        __syncthreads();
    }
}

// ---------------------------------------------------------------------------
// Kernel C: stage 2 — per group, softmax attention over the 31 other members
// grid = BB*GG blocks, 256 threads
// ---------------------------------------------------------------------------
struct SmemC {
    float W30a[64 * 64];   // W3_0[:,0:64]   (pc_enc part)
    float W30b[64 * 64];   // W3_0[:,128:192](pi_agg part)
    float W31[64 * 64];
    float W2d[64 * 4];     // Wxyz2[:,6:10]
    float B31[64];
    float Ef[64 * 32], Eg[64 * 32], F1[64 * 32], PAG[64 * 32];
    float X1[3 * 32];
    float PCE[64 * 32], T[64 * 32];
};

__global__ void kernelC(const float* __restrict__ xyz1, const float* __restrict__ wx2,
                        const float* __restrict__ w30, const float* __restrict__ w31,
                        const float* __restrict__ b31, float* __restrict__ out) {
    extern __shared__ float smem_raw[];
    SmemC& s = *reinterpret_cast<SmemC*>(smem_raw);
    int tid = threadIdx.x;
    int b = blockIdx.x / GG;
    int g = blockIdx.x % GG;
    int sb = g * MMG;

    for (int idx = tid; idx < 4096; idx += 256) {
        int c = idx >> 6, j = idx & 63;
        s.W30a[idx] = w30[c * 192 + j];
        s.W30b[idx] = w30[c * 192 + 128 + j];
        s.W31[idx] = w31[idx];
    }
    if (tid < 256) {
        int c = tid >> 2, j = tid & 3;
        s.W2d[tid] = wx2[c * 10 + 6 + j];
    }
    if (tid < 64) s.B31[tid] = b31[tid];
    for (int idx = tid; idx < 2048; idx += 256) {
        int c = idx >> 5, k = idx & 31;
        long base = (long)b * CC * SS + (long)c * SS + sb + k;
        s.Ef[idx] = g_Ef[base];
        s.Eg[idx] = g_Eg[base];
        s.F1[idx] = g_F1[base];
        s.PAG[idx] = g_agg[base];
    }
    for (int idx = tid; idx < 96; idx += 256) {
        int i = idx >> 5, k = idx & 31;
        s.X1[idx] = xyz1[b * 3 * SS + i * SS + sb + k];
    }
    __syncthreads();

    int lane = tid & 31;
    int cb = (tid >> 5) * 8;

    for (int sl = 0; sl < MMG; sl++) {
        float px0 = s.X1[sl], px1 = s.X1[32 + sl], px2 = s.X1[64 + sl];
        float d0 = s.X1[lane] - px0;
        float d1 = s.X1[32 + lane] - px1;
        float d2 = s.X1[64 + lane] - px2;
        float euc = sqrtf(d0 * d0 + d1 * d1 + d2 * d2 + 1e-20f);

        // pc_enc
#pragma unroll
        for (int i = 0; i < 8; i++) {
            int c = cb + i;
            float v = s.Ef[c * 32 + sl] + s.Eg[c * 32 + lane]
                    + s.W2d[c * 4 + 0] * d0 + s.W2d[c * 4 + 1] * d1
                    + s.W2d[c * 4 + 2] * d2 + s.W2d[c * 4 + 3] * euc;
            s.PCE[c * 32 + lane] = fmaxf(v, 0.f);
        }
        __syncthreads();

        // t = relu(W3_0 @ [pc_enc; feat1_bcast; pi_agg] + b3_0)
        float acc[8];
#pragma unroll
        for (int i = 0; i < 8; i++) acc[i] = s.F1[(cb + i) * 32 + sl];
        mm64_acc(acc, s.W30a, 64, cb, s.PCE, lane);
        mm64_acc(acc, s.W30b, 64, cb, s.PAG, lane);
#pragma unroll
        for (int i = 0; i < 8; i++) s.T[(cb + i) * 32 + lane] = fmaxf(acc[i], 0.f);
        __syncthreads();

        // logits = relu(W3_1 @ t + b3_1); mask self column; softmax; aggregate
#pragma unroll
        for (int i = 0; i < 8; i++) acc[i] = s.B31[cb + i];
        mm64_acc(acc, s.W31, 64, cb, s.T, lane);
#pragma unroll
        for (int i = 0; i < 8; i++) {
            float l = (lane == sl) ? -1e30f : fmaxf(acc[i], 0.f);
            float m = warp_rmax(l);
            float e = expf(l - m);
            float ssum = warp_rsum(e);
            float wgt = e / ssum;
            float v = warp_rsum(wgt * s.PAG[(cb + i) * 32 + lane]);
            if (lane == 0)
                out[(long)b * CC * SS + (long)(cb + i) * SS + sb + sl] = v;
        }
        __syncthreads();
    }
}

// ---------------------------------------------------------------------------
extern "C" void kernel_launch(void* const* d_in, const int* in_sizes, int n_in,
                              void* d_out, int out_size) {
    const float* xyz1 = (const float*)d_in[0];
    const float* feat1 = (const float*)d_in[1];
    const float* xyz2 = (const float*)d_in[2];
    const float* feat2 = (const float*)d_in[3];
    const float* w10 = (const float*)d_in[4];
    const float* b10 = (const float*)d_in[5];
    const float* w11 = (const float*)d_in[6];
    const float* b11 = (const float*)d_in[7];
    const float* wx1 = (const float*)d_in[8];
    const float* bx1 = (const float*)d_in[9];
    const float* wx2 = (const float*)d_in[10];
    const float* bx2 = (const float*)d_in[11];
    const float* w20 = (const float*)d_in[12];
    const float* b20 = (const float*)d_in[13];
    const float* w21 = (const float*)d_in[14];
    const float* b21 = (const float*)d_in[15];
    const float* w30 = (const float*)d_in[16];
    const float* b30 = (const float*)d_in[17];
    const float* w31 = (const float*)d_in[18];
    const float* b31 = (const float*)d_in[19];
    float* out = (float*)d_out;

    cudaFuncSetAttribute(kernelA, cudaFuncAttributeMaxDynamicSharedMemorySize, (int)sizeof(SmemA));
    cudaFuncSetAttribute(kernelB, cudaFuncAttributeMaxDynamicSharedMemorySize, (int)sizeof(SmemB));
    cudaFuncSetAttribute(kernelC, cudaFuncAttributeMaxDynamicSharedMemorySize, (int)sizeof(SmemC));

    kernelA<<<(BB * SS) / 32, 256, sizeof(SmemA)>>>(xyz1, feat1, xyz2, feat2,
                                                    w10, b10, wx1, bx1, wx2, bx2, w30, b30);
    kernelB<<<BB * GG, 256, sizeof(SmemB)>>>(xyz1, xyz2, w10, wx1,
                                             w11, b11, w20, b20, w21, b21);
    kernelC<<<BB * GG, 256, sizeof(SmemC)>>>(xyz1, wx2, w30, w31, b31, out);
}

// round 3
// speedup vs baseline: 1.5385x; 1.5385x over previous
#include <cuda_runtime.h>
#include <math.h>

// Problem constants
#define BB 2
#define SS 8192
#define CC 64
#define MMG 32
#define GG (SS / MMG)          // 256 groups per batch
#define BCS (BB * CC * SS)
#define WST 68                 // padded row stride for transposed weights

// Scratch (device globals — allocation-free)
__device__ float g_Pf[BCS];
__device__ float g_Qf[BCS];
__device__ float g_Pe[BCS];
__device__ float g_Qe[BCS];
__device__ float g_Ef[BCS];
__device__ float g_Eg[BCS];
__device__ float g_F1[BCS];
__device__ float g_agg[BCS];

typedef unsigned long long u64;

// ---------------------------------------------------------------------------
// packed fp32 helpers (Blackwell f32x2) + warp reduction
// ---------------------------------------------------------------------------
__device__ __forceinline__ void ffma2(u64& d, u64 a, u64 b) {
    asm("fma.rn.f32x2 %0, %1, %2, %0;" : "+l"(d) : "l"(a), "l"(b));
}
__device__ __forceinline__ u64 splat2(float a) {
    u64 r; asm("mov.b64 %0, {%1, %1};" : "=l"(r) : "f"(a)); return r;
}
__device__ __forceinline__ u64 pack2(float x, float y) {
    u64 r; asm("mov.b64 %0, {%1, %2};" : "=l"(r) : "f"(x), "f"(y)); return r;
}
__device__ __forceinline__ float2 unpack2(u64 v) {
    float2 r; asm("mov.b64 {%0, %1}, %2;" : "=f"(r.x), "=f"(r.y) : "l"(v)); return r;
}
// butterfly warp sum (sm_100 has no redux.f32)
__device__ __forceinline__ float warp_rsum(float v) {
#pragma unroll
    for (int o = 16; o > 0; o >>= 1) v += __shfl_xor_sync(0xffffffffu, v, o);
    return v;
}
// sum two independent values with interleaved butterflies (ILP-friendly)
__device__ __forceinline__ float2 warp_rsum2(float a, float b) {
#pragma unroll
    for (int o = 16; o > 0; o >>= 1) {
        a += __shfl_xor_sync(0xffffffffu, a, o);
        b += __shfl_xor_sync(0xffffffffu, b, o);
    }
    return make_float2(a, b);
}

// Packed matmul over K=64: acc{0,1}[i] += Wt[k][cb+2i..] * A{0,1}[k][lane]
__device__ __forceinline__ void mmT2(u64 acc0[4], u64 acc1[4],
                                     const float* __restrict__ sWt, int cb,
                                     const float* __restrict__ sA0,
                                     const float* __restrict__ sA1, int lane) {
#pragma unroll 8
    for (int k = 0; k < 64; k++) {
        ulonglong2 wlo = *reinterpret_cast<const ulonglong2*>(sWt + k * WST + cb);
        ulonglong2 whi = *reinterpret_cast<const ulonglong2*>(sWt + k * WST + cb + 4);
        u64 a0 = splat2(sA0[k * 32 + lane]);
        u64 a1 = splat2(sA1[k * 32 + lane]);
        ffma2(acc0[0], wlo.x, a0); ffma2(acc0[1], wlo.y, a0);
        ffma2(acc0[2], whi.x, a0); ffma2(acc0[3], whi.y, a0);
        ffma2(acc1[0], wlo.x, a1); ffma2(acc1[1], wlo.y, a1);
        ffma2(acc1[2], whi.x, a1); ffma2(acc1[3], whi.y, a1);
    }
}

// Single-activation variant (for kernel C precompute)
__device__ __forceinline__ void mmT1(u64 acc0[4],
                                     const float* __restrict__ sWt, int cb,
                                     const float* __restrict__ sA0, int lane) {
#pragma unroll 8
    for (int k = 0; k < 64; k++) {
        ulonglong2 wlo = *reinterpret_cast<const ulonglong2*>(sWt + k * WST + cb);
        ulonglong2 whi = *reinterpret_cast<const ulonglong2*>(sWt + k * WST + cb + 4);
        u64 a0 = splat2(sA0[k * 32 + lane]);
        ffma2(acc0[0], wlo.x, a0); ffma2(acc0[1], wlo.y, a0);
        ffma2(acc0[2], whi.x, a0); ffma2(acc0[3], whi.y, a0);
    }
}

// scalar helper used by kernel A
__device__ __forceinline__ void mm64_acc(float acc[8], const float* __restrict__ sW,
                                         int wstride, int cbase,
                                         const float* __restrict__ sA, int lane) {
#pragma unroll 4
    for (int q = 0; q < 16; q++) {
        float a0 = sA[(4 * q + 0) * 32 + lane];
        float a1 = sA[(4 * q + 1) * 32 + lane];
        float a2 = sA[(4 * q + 2) * 32 + lane];
        float a3 = sA[(4 * q + 3) * 32 + lane];
#pragma unroll
        for (int i = 0; i < 8; i++) {
            float4 w = *reinterpret_cast<const float4*>(&sW[(cbase + i) * wstride + 4 * q]);
            acc[i] = fmaf(w.x, a0, acc[i]);
            acc[i] = fmaf(w.y, a1, acc[i]);
            acc[i] = fmaf(w.z, a2, acc[i]);
            acc[i] = fmaf(w.w, a3, acc[i]);
        }
    }
}

// ---------------------------------------------------------------------------
// Kernel A: per-point linear projections (decomposed layer-0 parts)
// ---------------------------------------------------------------------------
struct SmemA {
    float Wpf[64 * 64];
    float Wqf[64 * 64];
    float Wf1[64 * 64];
    float W1x[64 * 8];
    float Wex[64 * 8];
    float W2x[64 * 8];
    float F1t[64 * 32];
    float F2t[64 * 32];
    float X1[3 * 32];
    float X2[3 * 32];
};

__global__ void kernelA(const float* __restrict__ xyz1, const float* __restrict__ feat1,
                        const float* __restrict__ xyz2, const float* __restrict__ feat2,
                        const float* __restrict__ w10, const float* __restrict__ b10,
                        const float* __restrict__ wx1, const float* __restrict__ bx1,
                        const float* __restrict__ wx2, const float* __restrict__ bx2,
                        const float* __restrict__ w30, const float* __restrict__ b30) {
    extern __shared__ float smem_raw[];
    SmemA& s = *reinterpret_cast<SmemA*>(smem_raw);
    int tid = threadIdx.x;
    int t = blockIdx.x;
    int b = t >> 8;
    int s0 = (t & 255) * 32;

    for (int idx = tid; idx < 4096; idx += 256) {
        int c = idx >> 6, j = idx & 63;
        s.Wpf[idx] = w10[c * 138 + 10 + j];
        s.Wqf[idx] = w10[c * 138 + 74 + j];
        s.Wf1[idx] = w30[c * 192 + 64 + j];
    }
    for (int idx = tid; idx < 384; idx += 256) {
        int c = idx / 6, j = idx % 6;
        s.W1x[c * 8 + j] = w10[c * 138 + j];
        s.Wex[c * 8 + j] = wx1[c * 10 + j];
        s.W2x[c * 8 + j] = wx2[c * 10 + j];
    }
    for (int idx = tid; idx < 2048; idx += 256) {
        int c = idx >> 5, k = idx & 31;
        s.F1t[idx] = feat1[b * CC * SS + c * SS + s0 + k];
        s.F2t[idx] = feat2[b * CC * SS + c * SS + s0 + k];
    }
    for (int idx = tid; idx < 96; idx += 256) {
        int i = idx >> 5, k = idx & 31;
        s.X1[idx] = xyz1[b * 3 * SS + i * SS + s0 + k];
        s.X2[idx] = xyz2[b * 3 * SS + i * SS + s0 + k];
    }
    __syncthreads();

    int lane = tid & 31;
    int cb = (tid >> 5) * 8;
    float x10 = s.X1[lane], x11 = s.X1[32 + lane], x12 = s.X1[64 + lane];
    float x20 = s.X2[lane], x21 = s.X2[32 + lane], x22 = s.X2[64 + lane];

    float accPf[8], accQf[8], accF1[8];
#pragma unroll
    for (int i = 0; i < 8; i++) {
        accPf[i] = __ldg(&b10[cb + i]);
        accQf[i] = 0.f;
        accF1[i] = __ldg(&b30[cb + i]);
    }
    mm64_acc(accPf, s.Wpf, 64, cb, s.F1t, lane);
    mm64_acc(accF1, s.Wf1, 64, cb, s.F1t, lane);
    mm64_acc(accQf, s.Wqf, 64, cb, s.F2t, lane);

#pragma unroll
    for (int i = 0; i < 8; i++) {
        int c = cb + i;
        long base = (long)b * CC * SS + (long)c * SS + s0 + lane;
        float pf = accPf[i] + s.W1x[c * 8 + 0] * x10 + s.W1x[c * 8 + 1] * x11 + s.W1x[c * 8 + 2] * x12;
        float qf = accQf[i] + s.W1x[c * 8 + 3] * x20 + s.W1x[c * 8 + 4] * x21 + s.W1x[c * 8 + 5] * x22;
        g_Pf[base] = pf;
        g_Qf[base] = qf;
        g_F1[base] = accF1[i];
        g_Pe[base] = __ldg(&bx1[c]) + s.Wex[c * 8 + 0] * x10 + s.Wex[c * 8 + 1] * x11 + s.Wex[c * 8 + 2] * x12;
        g_Qe[base] = s.Wex[c * 8 + 3] * x20 + s.Wex[c * 8 + 4] * x21 + s.Wex[c * 8 + 5] * x22;
        g_Ef[base] = __ldg(&bx2[c]) + s.W2x[c * 8 + 0] * x10 + s.W2x[c * 8 + 1] * x11 + s.W2x[c * 8 + 2] * x12;
        g_Eg[base] = s.W2x[c * 8 + 3] * x10 + s.W2x[c * 8 + 4] * x11 + s.W2x[c * 8 + 5] * x12;
    }
}

// ---------------------------------------------------------------------------
// Kernel B: stage 1, f32x2-packed, 2 s-points per pass, half-group blocks
// grid = BB*GG*2, 256 threads
// ---------------------------------------------------------------------------
struct SmemB {
    float W11t[64 * WST];
    float W20t[128 * WST];
    float W21t[64 * WST];
    float W1d[64 * 4];
    float Wed[64 * 4];
    float B11[64], B20[64], B21[64];
    float Pf[64 * 32], Pe[64 * 32];
    float X1[3 * 32], X2[3 * 32];
    float Ha[64 * 32], Hb[64 * 32];
    float PEa[64 * 32], PEb[64 * 32];
    float PNa[64 * 32], PNb[64 * 32];
};

__global__ void kernelB(const float* __restrict__ xyz1, const float* __restrict__ xyz2,
                        const float* __restrict__ w10, const float* __restrict__ wx1,
                        const float* __restrict__ w11, const float* __restrict__ b11,
                        const float* __restrict__ w20, const float* __restrict__ b20,
                        const float* __restrict__ w21, const float* __restrict__ b21) {
    extern __shared__ float smem_raw[];
    SmemB& s = *reinterpret_cast<SmemB*>(smem_raw);
    int tid = threadIdx.x;
    int bid = blockIdx.x;
    int b = bid >> 9;                 // 512 half-blocks per batch
    int g = (bid >> 1) & 255;
    int half = bid & 1;
    int sb = g * MMG;

    for (int idx = tid; idx < 4096; idx += 256) {
        int c = idx >> 6, k = idx & 63;
        s.W11t[k * WST + c] = w11[idx];
        s.W21t[k * WST + c] = w21[idx];
    }
    for (int idx = tid; idx < 8192; idx += 256) {
        int c = idx >> 7, k = idx & 127;
        s.W20t[k * WST + c] = w20[idx];
    }
    if (tid < 256) {
        int c = tid >> 2, j = tid & 3;
        s.W1d[tid] = w10[c * 138 + 6 + j];
        s.Wed[tid] = wx1[c * 10 + 6 + j];
    }
    if (tid < 64) {
        s.B11[tid] = b11[tid];
        s.B20[tid] = b20[tid];
        s.B21[tid] = b21[tid];
    }
    for (int idx = tid; idx < 2048; idx += 256) {
        int c = idx >> 5, k = idx & 31;
        long base = (long)b * CC * SS + (long)c * SS + sb + k;
        s.Pf[idx] = g_Pf[base];
        s.Pe[idx] = g_Pe[base];
    }
    for (int idx = tid; idx < 96; idx += 256) {
        int i = idx >> 5, k = idx & 31;
        s.X1[idx] = xyz1[b * 3 * SS + i * SS + sb + k];
        s.X2[idx] = xyz2[b * 3 * SS + i * SS + sb + k];
    }
    __syncthreads();

    int lane = tid & 31;
    int cb = (tid >> 5) * 8;
    long outbase = (long)b * CC * SS + sb;

    float qf[8], qe[8];
#pragma unroll
    for (int i = 0; i < 8; i++) {
        long base = (long)b * CC * SS + (long)(cb + i) * SS + sb + lane;
        qf[i] = __ldg(&g_Qf[base]);
        qe[i] = __ldg(&g_Qe[base]);
    }

    float nx0 = s.X2[lane], nx1 = s.X2[32 + lane], nx2 = s.X2[64 + lane];

    int sl0base = half * 16;
    for (int p = 0; p < 8; p++) {
        int sl0 = sl0base + 2 * p;
        int sl1 = sl0 + 1;

        // --- step 1: dynamic parts for both s ---
        {
            float pa0 = s.X1[sl0], pa1 = s.X1[32 + sl0], pa2 = s.X1[64 + sl0];
            float pb0 = s.X1[sl1], pb1 = s.X1[32 + sl1], pb2 = s.X1[64 + sl1];
            float da0 = nx0 - pa0, da1 = nx1 - pa1, da2 = nx2 - pa2;
            float db0 = nx0 - pb0, db1 = nx1 - pb1, db2 = nx2 - pb2;
            float ea = sqrtf(da0 * da0 + da1 * da1 + da2 * da2 + 1e-20f);
            float eb = sqrtf(db0 * db0 + db1 * db1 + db2 * db2 + 1e-20f);
#pragma unroll
            for (int i = 0; i < 8; i++) {
                int c = cb + i;
                float w0 = s.W1d[c * 4 + 0], w1 = s.W1d[c * 4 + 1], w2 = s.W1d[c * 4 + 2], w3 = s.W1d[c * 4 + 3];
                float ha = s.Pf[c * 32 + sl0] + qf[i] + w0 * da0 + w1 * da1 + w2 * da2 + w3 * ea;
                float hb = s.Pf[c * 32 + sl1] + qf[i] + w0 * db0 + w1 * db1 + w2 * db2 + w3 * eb;
                s.Ha[c * 32 + lane] = fmaxf(ha, 0.f);
                s.Hb[c * 32 + lane] = fmaxf(hb, 0.f);
                float v0 = s.Wed[c * 4 + 0], v1 = s.Wed[c * 4 + 1], v2 = s.Wed[c * 4 + 2], v3 = s.Wed[c * 4 + 3];
                float pea = s.Pe[c * 32 + sl0] + qe[i] + v0 * da0 + v1 * da1 + v2 * da2 + v3 * ea;
                float peb = s.Pe[c * 32 + sl1] + qe[i] + v0 * db0 + v1 * db1 + v2 * db2 + v3 * eb;
                s.PEa[c * 32 + lane] = fmaxf(pea, 0.f);
                s.PEb[c * 32 + lane] = fmaxf(peb, 0.f);
            }
        }
        __syncthreads();

        // --- step 2: pi_new = relu(W1_1 @ H + b1_1) ---
        u64 acc0[4], acc1[4];
#pragma unroll
        for (int i = 0; i < 4; i++) {
            u64 bv = *reinterpret_cast<const u64*>(&s.B11[cb + 2 * i]);
            acc0[i] = bv; acc1[i] = bv;
        }
        mmT2(acc0, acc1, s.W11t, cb, s.Ha, s.Hb, lane);
#pragma unroll
        for (int i = 0; i < 4; i++) {
            float2 ra = unpack2(acc0[i]), rb = unpack2(acc1[i]);
            s.PNa[(cb + 2 * i) * 32 + lane] = fmaxf(ra.x, 0.f);
            s.PNa[(cb + 2 * i + 1) * 32 + lane] = fmaxf(ra.y, 0.f);
            s.PNb[(cb + 2 * i) * 32 + lane] = fmaxf(rb.x, 0.f);
            s.PNb[(cb + 2 * i + 1) * 32 + lane] = fmaxf(rb.y, 0.f);
        }
        __syncthreads();

        // --- step 3: U = relu(W2_0 @ [PE; PN] + b2_0)  (into Ha/Hb) ---
#pragma unroll
        for (int i = 0; i < 4; i++) {
            u64 bv = *reinterpret_cast<const u64*>(&s.B20[cb + 2 * i]);
            acc0[i] = bv; acc1[i] = bv;
        }
        mmT2(acc0, acc1, s.W20t, cb, s.PEa, s.PEb, lane);
        mmT2(acc0, acc1, s.W20t + 64 * WST, cb, s.PNa, s.PNb, lane);
#pragma unroll
        for (int i = 0; i < 4; i++) {
            float2 ra = unpack2(acc0[i]), rb = unpack2(acc1[i]);
            s.Ha[(cb + 2 * i) * 32 + lane] = fmaxf(ra.x, 0.f);
            s.Ha[(cb + 2 * i + 1) * 32 + lane] = fmaxf(ra.y, 0.f);
            s.Hb[(cb + 2 * i) * 32 + lane] = fmaxf(rb.x, 0.f);
            s.Hb[(cb + 2 * i + 1) * 32 + lane] = fmaxf(rb.y, 0.f);
        }
        __syncthreads();

        // --- step 4: logits = relu(W2_1 @ U + b2_1); softmax; aggregate ---
#pragma unroll
        for (int i = 0; i < 4; i++) {
            u64 bv = *reinterpret_cast<const u64*>(&s.B21[cb + 2 * i]);
            acc0[i] = bv; acc1[i] = bv;
        }
        mmT2(acc0, acc1, s.W21t, cb, s.Ha, s.Hb, lane);
#pragma unroll
        for (int i = 0; i < 4; i++) {
            float2 la = unpack2(acc0[i]), lb = unpack2(acc1[i]);
            int c0 = cb + 2 * i, c1 = c0 + 1;
            float pn00 = s.PNa[c0 * 32 + lane];
            float pn01 = s.PNa[c1 * 32 + lane];
            float pn10 = s.PNb[c0 * 32 + lane];
            float pn11 = s.PNb[c1 * 32 + lane];
            float e00 = __expf(fmaxf(la.x, 0.f));
            float e01 = __expf(fmaxf(la.y, 0.f));
            float e10 = __expf(fmaxf(lb.x, 0.f));
            float e11 = __expf(fmaxf(lb.y, 0.f));
            float2 r00 = warp_rsum2(e00, e00 * pn00);
            float2 r01 = warp_rsum2(e01, e01 * pn01);
            float2 r10 = warp_rsum2(e10, e10 * pn10);
            float2 r11 = warp_rsum2(e11, e11 * pn11);
            if (lane == 0) {
                g_agg[outbase + (long)c0 * SS + sl0] = r00.y / r00.x;
                g_agg[outbase + (long)c1 * SS + sl0] = r01.y / r01.x;
                g_agg[outbase + (long)c0 * SS + sl1] = r10.y / r10.x;
                g_agg[outbase + (long)c1 * SS + sl1] = r11.y / r11.x;
            }
        }
        __syncthreads();
    }
}

// ---------------------------------------------------------------------------
// Kernel C: stage 2, f32x2-packed, s-independent W3_0b@pi_agg hoisted
// grid = BB*GG*2, 256 threads
// ---------------------------------------------------------------------------
struct SmemC {
    float W30at[64 * WST];
    float W30bt[64 * WST];
    float W31t[64 * WST];
    float W2d[64 * 4];
    float B31[64];
    float Ef[64 * 32], Eg[64 * 32], F1[64 * 32], PAG[64 * 32];
    float X1[3 * 32];
    float G[64 * 32];
    float Ta[64 * 32], Tb[64 * 32];
    float Pa[64 * 32], Pb[64 * 32];
};

__global__ void kernelC(const float* __restrict__ xyz1, const float* __restrict__ wx2,
                        const float* __restrict__ w30, const float* __restrict__ w31,
                        const float* __restrict__ b31, float* __restrict__ out) {
    extern __shared__ float smem_raw[];
    SmemC& s = *reinterpret_cast<SmemC*>(smem_raw);
    int tid = threadIdx.x;
    int bid = blockIdx.x;
    int b = bid >> 9;
    int g = (bid >> 1) & 255;
    int half = bid & 1;
    int sb = g * MMG;

    for (int idx = tid; idx < 4096; idx += 256) {
        int c = idx >> 6, j = idx & 63;
        s.W30at[j * WST + c] = w30[c * 192 + j];
        s.W30bt[j * WST + c] = w30[c * 192 + 128 + j];
        s.W31t[j * WST + c] = w31[idx];
    }
    if (tid < 256) {
        int c = tid >> 2, j = tid & 3;
        s.W2d[tid] = wx2[c * 10 + 6 + j];
    }
    if (tid < 64) s.B31[tid] = b31[tid];
    for (int idx = tid; idx < 2048; idx += 256) {
        int c = idx >> 5, k = idx & 31;
        long base = (long)b * CC * SS + (long)c * SS + sb + k;
        s.Ef[idx] = g_Ef[base];
        s.Eg[idx] = g_Eg[base];
        s.F1[idx] = g_F1[base];
        s.PAG[idx] = g_agg[base];
    }
    for (int idx = tid; idx < 96; idx += 256) {
        int i = idx >> 5, k = idx & 31;
        s.X1[idx] = xyz1[b * 3 * SS + i * SS + sb + k];
    }
    __syncthreads();

    int lane = tid & 31;
    int cb = (tid >> 5) * 8;
    long outbase = (long)b * CC * SS + sb;

    // --- precompute G = W3_0[:,128:192] @ pi_agg (s-independent) ---
    {
        u64 acc[4];
#pragma unroll
        for (int i = 0; i < 4; i++) acc[i] = 0ull;
        mmT1(acc, s.W30bt, cb, s.PAG, lane);
#pragma unroll
        for (int i = 0; i < 4; i++) {
            float2 r = unpack2(acc[i]);
            s.G[(cb + 2 * i) * 32 + lane] = r.x;
            s.G[(cb + 2 * i + 1) * 32 + lane] = r.y;
        }
    }
    __syncthreads();

    float nx0 = s.X1[lane], nx1 = s.X1[32 + lane], nx2 = s.X1[64 + lane];

    int sl0base = half * 16;
    for (int p = 0; p < 8; p++) {
        int sl0 = sl0base + 2 * p;
        int sl1 = sl0 + 1;

        // --- step 1: pc_enc for both s ---
        {
            float pa0 = s.X1[sl0], pa1 = s.X1[32 + sl0], pa2 = s.X1[64 + sl0];
            float pb0 = s.X1[sl1], pb1 = s.X1[32 + sl1], pb2 = s.X1[64 + sl1];
            float da0 = nx0 - pa0, da1 = nx1 - pa1, da2 = nx2 - pa2;
            float db0 = nx0 - pb0, db1 = nx1 - pb1, db2 = nx2 - pb2;
            float ea = sqrtf(da0 * da0 + da1 * da1 + da2 * da2 + 1e-20f);
            float eb = sqrtf(db0 * db0 + db1 * db1 + db2 * db2 + 1e-20f);
#pragma unroll
            for (int i = 0; i < 8; i++) {
                int c = cb + i;
                float w0 = s.W2d[c * 4 + 0], w1 = s.W2d[c * 4 + 1], w2 = s.W2d[c * 4 + 2], w3 = s.W2d[c * 4 + 3];
                float base_c = s.Eg[c * 32 + lane];
                float va = s.Ef[c * 32 + sl0] + base_c + w0 * da0 + w1 * da1 + w2 * da2 + w3 * ea;
                float vb = s.Ef[c * 32 + sl1] + base_c + w0 * db0 + w1 * db1 + w2 * db2 + w3 * eb;
                s.Pa[c * 32 + lane] = fmaxf(va, 0.f);
                s.Pb[c * 32 + lane] = fmaxf(vb, 0.f);
            }
        }
        __syncthreads();

        // --- step 2: T = relu(G + F1[.,sl] + W3_0a @ pc_enc) ---
        u64 acc0[4], acc1[4];
#pragma unroll
        for (int i = 0; i < 4; i++) {
            int c0 = cb + 2 * i, c1 = c0 + 1;
            float g0 = s.G[c0 * 32 + lane], g1 = s.G[c1 * 32 + lane];
            acc0[i] = pack2(g0 + s.F1[c0 * 32 + sl0], g1 + s.F1[c1 * 32 + sl0]);
            acc1[i] = pack2(g0 + s.F1[c0 * 32 + sl1], g1 + s.F1[c1 * 32 + sl1]);
        }
        mmT2(acc0, acc1, s.W30at, cb, s.Pa, s.Pb, lane);
#pragma unroll
        for (int i = 0; i < 4; i++) {
            float2 ra = unpack2(acc0[i]), rb = unpack2(acc1[i]);
            s.Ta[(cb + 2 * i) * 32 + lane] = fmaxf(ra.x, 0.f);
            s.Ta[(cb + 2 * i + 1) * 32 + lane] = fmaxf(ra.y, 0.f);
            s.Tb[(cb + 2 * i) * 32 + lane] = fmaxf(rb.x, 0.f);
            s.Tb[(cb + 2 * i + 1) * 32 + lane] = fmaxf(rb.y, 0.f);
        }
        __syncthreads();

        // --- step 3: logits = relu(W3_1 @ T + b3_1); masked softmax; aggregate ---
#pragma unroll
        for (int i = 0; i < 4; i++) {
            u64 bv = *reinterpret_cast<const u64*>(&s.B31[cb + 2 * i]);
            acc0[i] = bv; acc1[i] = bv;
        }
        mmT2(acc0, acc1, s.W31t, cb, s.Ta, s.Tb, lane);
#pragma unroll
        for (int i = 0; i < 4; i++) {
            float2 la = unpack2(acc0[i]), lb = unpack2(acc1[i]);
            int c0 = cb + 2 * i, c1 = c0 + 1;
            float pg0 = s.PAG[c0 * 32 + lane];
            float pg1 = s.PAG[c1 * 32 + lane];
            float e00 = (lane == sl0) ? 0.f : __expf(fmaxf(la.x, 0.f));
            float e01 = (lane == sl0) ? 0.f : __expf(fmaxf(la.y, 0.f));
            float e10 = (lane == sl1) ? 0.f : __expf(fmaxf(lb.x, 0.f));
            float e11 = (lane == sl1) ? 0.f : __expf(fmaxf(lb.y, 0.f));
            float2 r00 = warp_rsum2(e00, e00 * pg0);
            float2 r01 = warp_rsum2(e01, e01 * pg1);
            float2 r10 = warp_rsum2(e10, e10 * pg0);
            float2 r11 = warp_rsum2(e11, e11 * pg1);
            if (lane == 0) {
                out[outbase + (long)c0 * SS + sl0] = r00.y / r00.x;
                out[outbase + (long)c1 * SS + sl0] = r01.y / r01.x;
                out[outbase + (long)c0 * SS + sl1] = r10.y / r10.x;
                out[outbase + (long)c1 * SS + sl1] = r11.y / r11.x;
            }
        }
        __syncthreads();
    }
}

// ---------------------------------------------------------------------------
extern "C" void kernel_launch(void* const* d_in, const int* in_sizes, int n_in,
                              void* d_out, int out_size) {
    const float* xyz1 = (const float*)d_in[0];
    const float* feat1 = (const float*)d_in[1];
    const float* xyz2 = (const float*)d_in[2];
    const float* feat2 = (const float*)d_in[3];
    const float* w10 = (const float*)d_in[4];
    const float* b10 = (const float*)d_in[5];
    const float* w11 = (const float*)d_in[6];
    const float* b11 = (const float*)d_in[7];
    const float* wx1 = (const float*)d_in[8];
    const float* bx1 = (const float*)d_in[9];
    const float* wx2 = (const float*)d_in[10];
    const float* bx2 = (const float*)d_in[11];
    const float* w20 = (const float*)d_in[12];
    const float* b20 = (const float*)d_in[13];
    const float* w21 = (const float*)d_in[14];
    const float* b21 = (const float*)d_in[15];
    const float* w30 = (const float*)d_in[16];
    const float* b30 = (const float*)d_in[17];
    const float* w31 = (const float*)d_in[18];
    const float* b31 = (const float*)d_in[19];
    float* out = (float*)d_out;

    cudaFuncSetAttribute(kernelA, cudaFuncAttributeMaxDynamicSharedMemorySize, (int)sizeof(SmemA));
    cudaFuncSetAttribute(kernelB, cudaFuncAttributeMaxDynamicSharedMemorySize, (int)sizeof(SmemB));
    cudaFuncSetAttribute(kernelC, cudaFuncAttributeMaxDynamicSharedMemorySize, (int)sizeof(SmemC));

    kernelA<<<(BB * SS) / 32, 256, sizeof(SmemA)>>>(xyz1, feat1, xyz2, feat2,
                                                    w10, b10, wx1, bx1, wx2, bx2, w30, b30);
    kernelB<<<BB * GG * 2, 256, sizeof(SmemB)>>>(xyz1, xyz2, w10, wx1,
                                                 w11, b11, w20, b20, w21, b21);
    kernelC<<<BB * GG * 2, 256, sizeof(SmemC)>>>(xyz1, wx2, w30, w31, b31, out);
}